// round 12
// baseline (speedup 1.0000x reference)
#include <cuda_runtime.h>
#include <cuda_bf16.h>
#include <stdint.h>

// Problem constants (fixed-shape problem; runtime sizes used for loop bounds)
#define NMAX 100000
#define EMAX 1600000
#define HDIM 128
#define FDIM 128
#define CDIM 64
#define GMAX 512

// ---------------- scratch (__device__ globals; no runtime allocation) ------
__device__ __nv_bfloat16 g_h1b[(size_t)NMAX * HDIM];  // 25.6 MB node features (bf16)
__device__ float g_dinv[NMAX];
__device__ int   g_cnt[NMAX];                 // in-degree (edges only)
__device__ int   g_rowptr[NMAX];              // exclusive scan of g_cnt
__device__ int   g_pos[NMAX];                 // fill cursor (starts = rowptr)
__device__ int   g_csr[EMAX];                 // src ids grouped by dst
__device__ float g_readout[GMAX * HDIM];
__device__ float g_Wf[FDIM * HDIM];           // W_pre @ W_conv
__device__ float g_bf[HDIM];                  // b_pre @ W_conv
__device__ int   g_is64;
// decoupled-lookback scan state (reset by k_init every invocation)
__device__ int   g_scan_flag[128];            // 0=none, 1=aggregate, 2=inclusive
__device__ int   g_scan_agg[128];
__device__ int   g_scan_inc[128];

__device__ __forceinline__ int ld_idx(const void* p, long long i, bool w64) {
    return w64 ? (int)((const long long*)p)[i] : ((const int*)p)[i];
}

// ---------------- side stream for capture fork (static init, no dev alloc) --
static cudaStream_t s_side = nullptr;
static cudaEvent_t  s_ev1 = nullptr, s_ev2 = nullptr;
static bool s_fork_ok = false;
static struct SideInit {
    SideInit() {
        s_fork_ok =
            cudaStreamCreateWithFlags(&s_side, cudaStreamNonBlocking) == cudaSuccess &&
            cudaEventCreateWithFlags(&s_ev1, cudaEventDisableTiming) == cudaSuccess &&
            cudaEventCreateWithFlags(&s_ev2, cudaEventDisableTiming) == cudaSuccess;
    }
} s_side_init;

// ---------------- init: zero scratch + dtype detect + fuse W_pre@W_conv -----
__global__ void k_init(const int* __restrict__ ei_words,
                       const float* __restrict__ Wpre, const float* __restrict__ bpre,
                       const float* __restrict__ Wconv, int N, int G, int ZB) {
    if ((int)blockIdx.x < ZB) {
        int i = blockIdx.x * 256 + threadIdx.x;
        if (i == 0) {
            int acc = 0;
            for (int j = 1; j < 256; j += 2) acc |= ei_words[j];
            g_is64 = (acc == 0) ? 1 : 0;
        }
        if (i < 128) g_scan_flag[i] = 0;
        int total = N + G * HDIM;
        if (i >= total) return;
        if (i < N) g_cnt[i] = 0;
        else       g_readout[i - N] = 0.f;
    } else {
        int bi = blockIdx.x - ZB;                   // 0..64
        int i = bi * 2 + (threadIdx.x >> 7);        // row 0..129
        int j = threadIdx.x & 127;
        if (i < FDIM) {
            float a = 0.f;
            #pragma unroll 8
            for (int k = 0; k < HDIM; k++) a += Wpre[i * HDIM + k] * Wconv[k * HDIM + j];
            g_Wf[i * HDIM + j] = a;
        } else if (i == FDIM) {
            float a = 0.f;
            #pragma unroll 8
            for (int k = 0; k < HDIM; k++) a += bpre[k] * Wconv[k * HDIM + j];
            g_bf[j] = a;
        }
    }
}

// ---------------- main GEMM: h1 = x @ Wf + bf  (tf32 mma, persistent loop) --
#define XS_LD 132   // pad: A-frag bank = 4*g4 + t4 (+const)  -> 32 distinct
#define WS_LD 136   // pad: B-frag bank = 8*t4 + g4 (+const)  -> 32 distinct
#define GEMM_SMEM ((128 * WS_LD + 128 + 64 * XS_LD) * 4)
#define GEMM_GRID 296

__device__ __forceinline__ uint32_t f2tf32(float f) {
    uint32_t o;
    asm("cvt.rna.tf32.f32 %0, %1;" : "=r"(o) : "f"(f));
    return o;
}

__global__ __launch_bounds__(256) void k_gemm_mma(const float* __restrict__ x,
                                                  int N, int numTiles) {
    extern __shared__ float smf[];
    float* ws  = smf;                        // [128][WS_LD]
    float* bfs = smf + 128 * WS_LD;          // [128]
    float* xs  = smf + 128 * WS_LD + 128;    // [64][XS_LD]

    int tid  = threadIdx.x;
    int warp = tid >> 5, lane = tid & 31;
    int g4 = lane >> 2, t4 = lane & 3;       // groupID (0..7), tid-in-group (0..3)
    int wm = warp >> 2, wn = warp & 3;       // warp tile coords: 2 (m) x 4 (n)

    // load Wf (128x128) -> ws, tf32-rounded  (ONCE per CTA)
    #pragma unroll
    for (int i = 0; i < 16; i++) {
        int lin = tid + i * 256;             // float4 index
        int r = lin >> 5, c = (lin & 31) * 4;
        float4 v = *(const float4*)&g_Wf[r * HDIM + c];
        uint32_t* dst = (uint32_t*)&ws[r * WS_LD + c];
        dst[0] = f2tf32(v.x); dst[1] = f2tf32(v.y);
        dst[2] = f2tf32(v.z); dst[3] = f2tf32(v.w);
    }
    if (tid < HDIM) bfs[tid] = g_bf[tid];

    for (int tile = blockIdx.x; tile < numTiles; tile += gridDim.x) {
        int rb = tile * 64;
        __syncthreads();   // prior iteration's compute done before xs overwrite
        #pragma unroll
        for (int i = 0; i < 8; i++) {
            int lin = tid + i * 256;
            int r = lin >> 5, c = (lin & 31) * 4;
            int grow = rb + r;
            float4 v = (grow < N) ? *(const float4*)&x[(size_t)grow * FDIM + c]
                                  : make_float4(0.f, 0.f, 0.f, 0.f);
            uint32_t* dst = (uint32_t*)&xs[r * XS_LD + c];
            dst[0] = f2tf32(v.x); dst[1] = f2tf32(v.y);
            dst[2] = f2tf32(v.z); dst[3] = f2tf32(v.w);
        }
        __syncthreads();

        float acc[2][4][4];
        #pragma unroll
        for (int mt = 0; mt < 2; mt++)
            #pragma unroll
            for (int nt = 0; nt < 4; nt++)
                #pragma unroll
                for (int q = 0; q < 4; q++) acc[mt][nt][q] = 0.f;

        #pragma unroll
        for (int ks = 0; ks < 16; ks++) {
            int k0 = ks * 8;
            uint32_t a[2][4];
            #pragma unroll
            for (int mt = 0; mt < 2; mt++) {
                int r0 = wm * 32 + mt * 16;
                a[mt][0] = __float_as_uint(xs[(r0 + g4    ) * XS_LD + k0 + t4    ]);
                a[mt][1] = __float_as_uint(xs[(r0 + g4 + 8) * XS_LD + k0 + t4    ]);
                a[mt][2] = __float_as_uint(xs[(r0 + g4    ) * XS_LD + k0 + t4 + 4]);
                a[mt][3] = __float_as_uint(xs[(r0 + g4 + 8) * XS_LD + k0 + t4 + 4]);
            }
            #pragma unroll
            for (int nt = 0; nt < 4; nt++) {
                int nb = wn * 32 + nt * 8 + g4;
                uint32_t b0 = __float_as_uint(ws[(k0 + t4    ) * WS_LD + nb]);
                uint32_t b1 = __float_as_uint(ws[(k0 + t4 + 4) * WS_LD + nb]);
                #pragma unroll
                for (int mt = 0; mt < 2; mt++) {
                    asm volatile(
                        "mma.sync.aligned.m16n8k8.row.col.f32.tf32.tf32.f32 "
                        "{%0,%1,%2,%3}, {%4,%5,%6,%7}, {%8,%9}, {%0,%1,%2,%3};"
                        : "+f"(acc[mt][nt][0]), "+f"(acc[mt][nt][1]),
                          "+f"(acc[mt][nt][2]), "+f"(acc[mt][nt][3])
                        : "r"(a[mt][0]), "r"(a[mt][1]), "r"(a[mt][2]), "r"(a[mt][3]),
                          "r"(b0), "r"(b1));
                }
            }
        }

        #pragma unroll
        for (int mt = 0; mt < 2; mt++) {
            int r0 = rb + wm * 32 + mt * 16 + g4;
            #pragma unroll
            for (int nt = 0; nt < 4; nt++) {
                int col = wn * 32 + nt * 8 + t4 * 2;
                float bv0 = bfs[col], bv1 = bfs[col + 1];
                if (r0 < N) {
                    __nv_bfloat162 o = __float22bfloat162_rn(
                        make_float2(acc[mt][nt][0] + bv0, acc[mt][nt][1] + bv1));
                    *(__nv_bfloat162*)&g_h1b[(size_t)r0 * HDIM + col] = o;
                }
                if (r0 + 8 < N) {
                    __nv_bfloat162 o = __float22bfloat162_rn(
                        make_float2(acc[mt][nt][2] + bv0, acc[mt][nt][3] + bv1));
                    *(__nv_bfloat162*)&g_h1b[(size_t)(r0 + 8) * HDIM + col] = o;
                }
            }
        }
    }
}

// ---------------- degree count (4 edges/thread, batched atomics) ------------
__global__ void k_count(const void* __restrict__ ei, int E) {
    bool w64 = g_is64 != 0;
    int i = (blockIdx.x * blockDim.x + threadIdx.x) * 4;
    if (i >= E) return;
    int n = min(4, E - i);
    int d[4];
    #pragma unroll
    for (int q = 0; q < 4; q++) if (q < n) d[q] = ld_idx(ei, (long long)E + i + q, w64);
    #pragma unroll
    for (int q = 0; q < 4; q++) if (q < n) atomicAdd(&g_cnt[d[q]], 1);
}

// ---------------- single-kernel exclusive scan (decoupled lookback) ---------
// 98 blocks of 1024 — all resident in one wave (98 < 148 SMs), so spinning on
// predecessor flags cannot deadlock. Produces: g_dinv, g_rowptr, g_pos.
__global__ __launch_bounds__(1024) void k_scan(int N) {
    __shared__ int sm[1024];
    __shared__ int s_exc;
    int b = blockIdx.x;
    int i = b * 1024 + threadIdx.x;
    int v = (i < N) ? g_cnt[i] : 0;
    if (i < N) g_dinv[i] = rsqrtf((float)(v + 1));
    sm[threadIdx.x] = v;
    __syncthreads();
    for (int off = 1; off < 1024; off <<= 1) {
        int t = (threadIdx.x >= off) ? sm[threadIdx.x - off] : 0;
        __syncthreads();
        sm[threadIdx.x] += t;
        __syncthreads();
    }
    int incl  = sm[threadIdx.x];
    int total = sm[1023];

    if (threadIdx.x == 0) {
        if (b == 0) {
            g_scan_inc[0] = total;
            __threadfence();
            atomicExch(&g_scan_flag[0], 2);
            s_exc = 0;
        } else {
            g_scan_agg[b] = total;
            __threadfence();
            atomicExch(&g_scan_flag[b], 1);
        }
    }
    if (b > 0) {
        if (threadIdx.x < 32) {
            int lane = threadIdx.x;
            int exc = 0;
            int look = b - 1;
            while (true) {
                int idx = look - lane;                 // window [look-31, look]
                int f = (idx >= 0) ? atomicAdd(&g_scan_flag[idx], 0) : 1;
                unsigned ready = __ballot_sync(0xffffffffu, f >= 1);
                if (ready != 0xffffffffu) continue;    // spin until window visible
                unsigned incmask = __ballot_sync(0xffffffffu, idx >= 0 && f == 2);
                __threadfence();
                if (incmask) {
                    int srcLane = __ffs(incmask) - 1;  // smallest lane = largest idx w/ inclusive
                    int contrib = 0;
                    if (idx >= 0) {
                        if (lane < srcLane)       contrib = g_scan_agg[idx];
                        else if (lane == srcLane) contrib = g_scan_inc[idx];
                    }
                    #pragma unroll
                    for (int o = 16; o; o >>= 1) contrib += __shfl_xor_sync(0xffffffffu, contrib, o);
                    exc += contrib;
                    break;
                } else {
                    int contrib = (idx >= 0) ? g_scan_agg[idx] : 0;
                    #pragma unroll
                    for (int o = 16; o; o >>= 1) contrib += __shfl_xor_sync(0xffffffffu, contrib, o);
                    exc += contrib;
                    look -= 32;
                }
            }
            if (lane == 0) {
                s_exc = exc;
                g_scan_inc[b] = exc + total;
                __threadfence();
                atomicExch(&g_scan_flag[b], 2);
            }
        }
    }
    __syncthreads();
    int exc = s_exc;
    if (i < N) {
        int r = exc + incl - v;     // exclusive prefix
        g_rowptr[i] = r;
        g_pos[i] = r;
    }
}

// ---------------- CSR fill (4 edges/thread, batched) ------------------------
__global__ void k_fill(const void* __restrict__ ei, int E) {
    bool w64 = g_is64 != 0;
    int i = (blockIdx.x * blockDim.x + threadIdx.x) * 4;
    if (i >= E) return;
    int n = min(4, E - i);
    int s[4], d[4], pos[4];
    #pragma unroll
    for (int q = 0; q < 4; q++) if (q < n) {
        s[q] = ld_idx(ei, i + q, w64);
        d[q] = ld_idx(ei, (long long)E + i + q, w64);
    }
    #pragma unroll
    for (int q = 0; q < 4; q++) if (q < n) pos[q] = atomicAdd(&g_pos[d[q]], 1);
    #pragma unroll
    for (int q = 0; q < 4; q++) if (q < n) g_csr[pos[q]] = s[q];
}

// ---------------- propagation + LayerNorm + ReLU + pooling ------------------
__device__ __forceinline__ float4 bf16x4_to_f4(uint2 raw) {
    __nv_bfloat162 lo = *(__nv_bfloat162*)&raw.x;
    __nv_bfloat162 hi = *(__nv_bfloat162*)&raw.y;
    float2 a = __bfloat1622float2(lo);
    float2 b = __bfloat1622float2(hi);
    return make_float4(a.x, a.y, b.x, b.y);
}

__global__ __launch_bounds__(256) void k_main(const void* __restrict__ batch,
                                              const float* __restrict__ b_conv,
                                              const float* __restrict__ gamma,
                                              const float* __restrict__ beta,
                                              int N) {
    const bool w64 = g_is64 != 0;
    int warp = threadIdx.x >> 5, lane = threadIdx.x & 31;
    int v = blockIdx.x * 8 + warp;
    __shared__ int   sgph[8];
    __shared__ float sstage[8][HDIM];   // conflict-free pooling stage (no atomics)
    __shared__ int   s_same;

    bool valid = v < N;
    float4 y = make_float4(0.f, 0.f, 0.f, 0.f);
    int g = -1;
    const char* h1base = (const char*)g_h1b;

    if (valid) {
        float dv = g_dinv[v];
        float4 acc;
        {
            uint2 raw = *(const uint2*)(h1base + ((size_t)v << 8) + lane * 8);
            float4 hv = bf16x4_to_f4(raw);
            float sw = dv * dv;
            acc = make_float4(sw * hv.x, sw * hv.y, sw * hv.z, sw * hv.w);
        }
        int start = g_rowptr[v], cnt = g_cnt[v];
        for (int base = 0; base < cnt; base += 32) {
            int e = base + lane;
            int off = 0; float ww = 0.f;
            if (e < cnt) {
                int s = g_csr[start + e];
                off = s << 8;                   // byte offset: 128 * 2B = 256B rows
                ww = g_dinv[s] * dv;
            }
            int m = min(32, cnt - base);
            int j = 0;
            for (; j + 8 <= m; j += 8) {
                uint2 raw[8]; float wj[8];
                #pragma unroll
                for (int q = 0; q < 8; q++) {
                    int oq = __shfl_sync(0xffffffffu, off, j + q);
                    wj[q]  = __shfl_sync(0xffffffffu, ww, j + q);
                    raw[q] = *(const uint2*)(h1base + oq + lane * 8);
                }
                #pragma unroll
                for (int q = 0; q < 8; q++) {
                    float4 hs = bf16x4_to_f4(raw[q]);
                    acc.x += wj[q] * hs.x; acc.y += wj[q] * hs.y;
                    acc.z += wj[q] * hs.z; acc.w += wj[q] * hs.w;
                }
            }
            for (; j < m; j++) {
                int   oq = __shfl_sync(0xffffffffu, off, j);
                float wj = __shfl_sync(0xffffffffu, ww, j);
                uint2 raw = *(const uint2*)(h1base + oq + lane * 8);
                float4 hs = bf16x4_to_f4(raw);
                acc.x += wj * hs.x; acc.y += wj * hs.y;
                acc.z += wj * hs.z; acc.w += wj * hs.w;
            }
        }
        {
            float4 bc = *(const float4*)&b_conv[lane * 4];
            acc.x += bc.x; acc.y += bc.y; acc.z += bc.z; acc.w += bc.w;
        }
        // LayerNorm over 128 features (4 per lane)
        float sum = acc.x + acc.y + acc.z + acc.w;
        #pragma unroll
        for (int o = 16; o; o >>= 1) sum += __shfl_xor_sync(0xffffffffu, sum, o);
        float mu = sum * (1.f / 128.f);
        float cx = acc.x - mu, cy = acc.y - mu, cz = acc.z - mu, cw = acc.w - mu;
        float sq = cx * cx + cy * cy + cz * cz + cw * cw;
        #pragma unroll
        for (int o = 16; o; o >>= 1) sq += __shfl_xor_sync(0xffffffffu, sq, o);
        float inv = rsqrtf(sq * (1.f / 128.f) + 1e-5f);
        float4 ga = *(const float4*)&gamma[lane * 4];
        float4 be = *(const float4*)&beta[lane * 4];
        y.x = fmaxf(0.f, ga.x * cx * inv + be.x);
        y.y = fmaxf(0.f, ga.y * cy * inv + be.y);
        y.z = fmaxf(0.f, ga.z * cz * inv + be.z);
        y.w = fmaxf(0.f, ga.w * cw * inv + be.w);
        g = ld_idx(batch, v, w64);
    }

    // pooling: stage per-warp rows (zeros if invalid), tree-reduce, 1 atomic/feature
    sgph[warp] = valid ? g : -1;
    *(float4*)&sstage[warp][lane * 4] = y;
    __syncthreads();
    if (threadIdx.x == 0) {
        int g0 = -1; bool same = true;
        for (int i = 0; i < 8; i++) {
            int gi = sgph[i];
            if (gi >= 0) { if (g0 < 0) g0 = gi; else if (gi != g0) same = false; }
        }
        s_same = same ? g0 : -2;   // -2 = mixed graphs; g0 = -1 if no valid warp
    }
    __syncthreads();
    int smflag = s_same;
    if (smflag == -2) {
        if (valid) {
            float* ro = &g_readout[(size_t)g * HDIM + lane * 4];
            atomicAdd(ro + 0, y.x); atomicAdd(ro + 1, y.y);
            atomicAdd(ro + 2, y.z); atomicAdd(ro + 3, y.w);
        }
    } else if (smflag >= 0 && threadIdx.x < HDIM) {
        float a = 0.f;
        #pragma unroll
        for (int w = 0; w < 8; w++) a += sstage[w][threadIdx.x];
        atomicAdd(&g_readout[(size_t)smflag * HDIM + threadIdx.x], a);
    }
}

// ---------------- epilogue GEMM: out = readout @ W_post + b_post ------------
__global__ void k_out(const float* __restrict__ Wp, const float* __restrict__ bp,
                      float* __restrict__ out) {
    __shared__ float r[HDIM];
    int b = blockIdx.x, j = threadIdx.x;   // 64 threads
    r[j]      = g_readout[(size_t)b * HDIM + j];
    r[j + 64] = g_readout[(size_t)b * HDIM + j + 64];
    __syncthreads();
    float acc = bp[j];
    #pragma unroll 8
    for (int k = 0; k < HDIM; k++) acc += r[k] * Wp[k * CDIM + j];
    out[b * CDIM + j] = acc;
}

// ---------------- launch ----------------------------------------------------
extern "C" void kernel_launch(void* const* d_in, const int* in_sizes, int n_in,
                              void* d_out, int out_size) {
    const float* x      = (const float*)d_in[0];
    const void*  ei     = d_in[1];
    const void*  batch  = d_in[2];
    const float* W_pre  = (const float*)d_in[3];
    const float* b_pre  = (const float*)d_in[4];
    const float* W_conv = (const float*)d_in[5];
    const float* b_conv = (const float*)d_in[6];
    const float* gamma  = (const float*)d_in[7];
    const float* beta   = (const float*)d_in[8];
    const float* W_post = (const float*)d_in[9];
    const float* b_post = (const float*)d_in[10];

    int N = in_sizes[0] / FDIM;
    int E = in_sizes[1] / 2;
    int G = out_size / CDIM;
    if (N > NMAX) N = NMAX;
    if (E > EMAX) E = EMAX;
    if (G > GMAX) G = GMAX;
    int NB = (N + 1023) / 1024;
    int numTiles = (N + 63) / 64;

    cudaFuncSetAttribute(k_gemm_mma, cudaFuncAttributeMaxDynamicSharedMemorySize, GEMM_SMEM);

    {
        int ZB = (N + G * HDIM + 255) / 256;
        k_init<<<ZB + 65, 256>>>((const int*)ei, W_pre, b_pre, W_conv, N, G, ZB);
    }

    if (s_fork_ok) {
        // fork: GEMM on side stream, CSR build on main stream, rejoin before k_main
        cudaEventRecord(s_ev1, 0);
        cudaStreamWaitEvent(s_side, s_ev1, 0);
        k_gemm_mma<<<GEMM_GRID, 256, GEMM_SMEM, s_side>>>(x, N, numTiles);
        cudaEventRecord(s_ev2, s_side);

        k_count<<<(E / 4 + 255) / 256, 256>>>(ei, E);
        k_scan<<<NB, 1024>>>(N);
        k_fill<<<(E / 4 + 255) / 256, 256>>>(ei, E);

        cudaStreamWaitEvent(0, s_ev2, 0);
    } else {
        k_gemm_mma<<<GEMM_GRID, 256, GEMM_SMEM>>>(x, N, numTiles);
        k_count<<<(E / 4 + 255) / 256, 256>>>(ei, E);
        k_scan<<<NB, 1024>>>(N);
        k_fill<<<(E / 4 + 255) / 256, 256>>>(ei, E);
    }

    k_main<<<(N + 7) / 8, 256>>>(batch, b_conv, gamma, beta, N);
    k_out<<<G, CDIM>>>(W_post, b_post, (float*)d_out);
}

// round 13
// speedup vs baseline: 1.0854x; 1.0854x over previous
#include <cuda_runtime.h>
#include <cuda_bf16.h>
#include <stdint.h>

// Problem constants (fixed-shape problem; runtime sizes used for loop bounds)
#define NMAX 100000
#define EMAX 1600000
#define HDIM 128
#define FDIM 128
#define CDIM 64
#define GMAX 512

// ---------------- scratch (__device__ globals; no runtime allocation) ------
__device__ __nv_bfloat16 g_h1b[(size_t)NMAX * HDIM];  // 25.6 MB node features (bf16)
__device__ float g_dinv[NMAX];
__device__ int   g_cnt[NMAX];                 // in-degree (edges only)
__device__ int   g_rowptr[NMAX];              // exclusive scan of g_cnt
__device__ int   g_pos[NMAX];                 // fill cursor (starts = rowptr)
__device__ int   g_csr[EMAX];                 // src ids grouped by dst
__device__ int   g_blocksums[256];
__device__ float g_readout[GMAX * HDIM];
__device__ float g_Wf[FDIM * HDIM];           // W_pre @ W_conv
__device__ float g_bf[HDIM];                  // b_pre @ W_conv
__device__ int   g_is64;

__device__ __forceinline__ int ld_idx(const void* p, long long i, bool w64) {
    return w64 ? (int)((const long long*)p)[i] : ((const int*)p)[i];
}

// ---------------- side stream for capture fork (static init, no dev alloc) --
static cudaStream_t s_side = nullptr;
static cudaEvent_t  s_ev1 = nullptr, s_ev2 = nullptr;
static bool s_fork_ok = false;
static struct SideInit {
    SideInit() {
        s_fork_ok =
            cudaStreamCreateWithFlags(&s_side, cudaStreamNonBlocking) == cudaSuccess &&
            cudaEventCreateWithFlags(&s_ev1, cudaEventDisableTiming) == cudaSuccess &&
            cudaEventCreateWithFlags(&s_ev2, cudaEventDisableTiming) == cudaSuccess;
    }
} s_side_init;

// ---------------- init: zero scratch + dtype detect + fuse W_pre@W_conv -----
__global__ void k_init(const int* __restrict__ ei_words,
                       const float* __restrict__ Wpre, const float* __restrict__ bpre,
                       const float* __restrict__ Wconv, int N, int G, int ZB) {
    if ((int)blockIdx.x < ZB) {
        int i = blockIdx.x * 256 + threadIdx.x;
        if (i == 0) {
            int acc = 0;
            for (int j = 1; j < 256; j += 2) acc |= ei_words[j];
            g_is64 = (acc == 0) ? 1 : 0;
        }
        int total = N + G * HDIM;
        if (i >= total) return;
        if (i < N) g_cnt[i] = 0;
        else       g_readout[i - N] = 0.f;
    } else {
        int bi = blockIdx.x - ZB;                   // 0..64
        int i = bi * 2 + (threadIdx.x >> 7);        // row 0..129
        int j = threadIdx.x & 127;
        if (i < FDIM) {
            float a = 0.f;
            #pragma unroll 8
            for (int k = 0; k < HDIM; k++) a += Wpre[i * HDIM + k] * Wconv[k * HDIM + j];
            g_Wf[i * HDIM + j] = a;
        } else if (i == FDIM) {
            float a = 0.f;
            #pragma unroll 8
            for (int k = 0; k < HDIM; k++) a += bpre[k] * Wconv[k * HDIM + j];
            g_bf[j] = a;
        }
    }
}

// ---------------- main GEMM: h1 = x @ Wf + bf  (tf32 mma, persistent loop) --
#define XS_LD 132   // pad: A-frag bank = 4*g4 + t4 (+const)  -> 32 distinct
#define WS_LD 136   // pad: B-frag bank = 8*t4 + g4 (+const)  -> 32 distinct
#define GEMM_SMEM ((128 * WS_LD + 128 + 64 * XS_LD) * 4)
#define GEMM_GRID 296

__device__ __forceinline__ uint32_t f2tf32(float f) {
    uint32_t o;
    asm("cvt.rna.tf32.f32 %0, %1;" : "=r"(o) : "f"(f));
    return o;
}

__global__ __launch_bounds__(256) void k_gemm_mma(const float* __restrict__ x,
                                                  int N, int numTiles) {
    extern __shared__ float smf[];
    float* ws  = smf;                        // [128][WS_LD]
    float* bfs = smf + 128 * WS_LD;          // [128]
    float* xs  = smf + 128 * WS_LD + 128;    // [64][XS_LD]

    int tid  = threadIdx.x;
    int warp = tid >> 5, lane = tid & 31;
    int g4 = lane >> 2, t4 = lane & 3;
    int wm = warp >> 2, wn = warp & 3;

    #pragma unroll
    for (int i = 0; i < 16; i++) {
        int lin = tid + i * 256;
        int r = lin >> 5, c = (lin & 31) * 4;
        float4 v = *(const float4*)&g_Wf[r * HDIM + c];
        uint32_t* dst = (uint32_t*)&ws[r * WS_LD + c];
        dst[0] = f2tf32(v.x); dst[1] = f2tf32(v.y);
        dst[2] = f2tf32(v.z); dst[3] = f2tf32(v.w);
    }
    if (tid < HDIM) bfs[tid] = g_bf[tid];

    for (int tile = blockIdx.x; tile < numTiles; tile += gridDim.x) {
        int rb = tile * 64;
        __syncthreads();
        #pragma unroll
        for (int i = 0; i < 8; i++) {
            int lin = tid + i * 256;
            int r = lin >> 5, c = (lin & 31) * 4;
            int grow = rb + r;
            float4 v = (grow < N) ? *(const float4*)&x[(size_t)grow * FDIM + c]
                                  : make_float4(0.f, 0.f, 0.f, 0.f);
            uint32_t* dst = (uint32_t*)&xs[r * XS_LD + c];
            dst[0] = f2tf32(v.x); dst[1] = f2tf32(v.y);
            dst[2] = f2tf32(v.z); dst[3] = f2tf32(v.w);
        }
        __syncthreads();

        float acc[2][4][4];
        #pragma unroll
        for (int mt = 0; mt < 2; mt++)
            #pragma unroll
            for (int nt = 0; nt < 4; nt++)
                #pragma unroll
                for (int q = 0; q < 4; q++) acc[mt][nt][q] = 0.f;

        #pragma unroll
        for (int ks = 0; ks < 16; ks++) {
            int k0 = ks * 8;
            uint32_t a[2][4];
            #pragma unroll
            for (int mt = 0; mt < 2; mt++) {
                int r0 = wm * 32 + mt * 16;
                a[mt][0] = __float_as_uint(xs[(r0 + g4    ) * XS_LD + k0 + t4    ]);
                a[mt][1] = __float_as_uint(xs[(r0 + g4 + 8) * XS_LD + k0 + t4    ]);
                a[mt][2] = __float_as_uint(xs[(r0 + g4    ) * XS_LD + k0 + t4 + 4]);
                a[mt][3] = __float_as_uint(xs[(r0 + g4 + 8) * XS_LD + k0 + t4 + 4]);
            }
            #pragma unroll
            for (int nt = 0; nt < 4; nt++) {
                int nb = wn * 32 + nt * 8 + g4;
                uint32_t b0 = __float_as_uint(ws[(k0 + t4    ) * WS_LD + nb]);
                uint32_t b1 = __float_as_uint(ws[(k0 + t4 + 4) * WS_LD + nb]);
                #pragma unroll
                for (int mt = 0; mt < 2; mt++) {
                    asm volatile(
                        "mma.sync.aligned.m16n8k8.row.col.f32.tf32.tf32.f32 "
                        "{%0,%1,%2,%3}, {%4,%5,%6,%7}, {%8,%9}, {%0,%1,%2,%3};"
                        : "+f"(acc[mt][nt][0]), "+f"(acc[mt][nt][1]),
                          "+f"(acc[mt][nt][2]), "+f"(acc[mt][nt][3])
                        : "r"(a[mt][0]), "r"(a[mt][1]), "r"(a[mt][2]), "r"(a[mt][3]),
                          "r"(b0), "r"(b1));
                }
            }
        }

        #pragma unroll
        for (int mt = 0; mt < 2; mt++) {
            int r0 = rb + wm * 32 + mt * 16 + g4;
            #pragma unroll
            for (int nt = 0; nt < 4; nt++) {
                int col = wn * 32 + nt * 8 + t4 * 2;
                float bv0 = bfs[col], bv1 = bfs[col + 1];
                if (r0 < N) {
                    __nv_bfloat162 o = __float22bfloat162_rn(
                        make_float2(acc[mt][nt][0] + bv0, acc[mt][nt][1] + bv1));
                    *(__nv_bfloat162*)&g_h1b[(size_t)r0 * HDIM + col] = o;
                }
                if (r0 + 8 < N) {
                    __nv_bfloat162 o = __float22bfloat162_rn(
                        make_float2(acc[mt][nt][2] + bv0, acc[mt][nt][3] + bv1));
                    *(__nv_bfloat162*)&g_h1b[(size_t)(r0 + 8) * HDIM + col] = o;
                }
            }
        }
    }
}

// ---------------- degree count (4 edges/thread, batched atomics) ------------
__global__ void k_count(const void* __restrict__ ei, int E) {
    bool w64 = g_is64 != 0;
    int i = (blockIdx.x * blockDim.x + threadIdx.x) * 4;
    if (i >= E) return;
    int n = min(4, E - i);
    int d[4];
    #pragma unroll
    for (int q = 0; q < 4; q++) if (q < n) d[q] = ld_idx(ei, (long long)E + i + q, w64);
    #pragma unroll
    for (int q = 0; q < 4; q++) if (q < n) atomicAdd(&g_cnt[d[q]], 1);
}

// ---------------- exclusive scan of g_cnt -> g_rowptr (+ dinv fused) -------
__global__ void k_scan1(int N) {
    __shared__ int sm[1024];
    int i = blockIdx.x * 1024 + threadIdx.x;
    int v = (i < N) ? g_cnt[i] : 0;
    if (i < N) g_dinv[i] = rsqrtf((float)(v + 1));
    sm[threadIdx.x] = v;
    __syncthreads();
    for (int off = 1; off < 1024; off <<= 1) {
        int t = (threadIdx.x >= off) ? sm[threadIdx.x - off] : 0;
        __syncthreads();
        sm[threadIdx.x] += t;
        __syncthreads();
    }
    if (i < N) g_rowptr[i] = sm[threadIdx.x] - v;
    if (threadIdx.x == 1023) g_blocksums[blockIdx.x] = sm[1023];
}

__global__ void k_scan2(int NB) {
    __shared__ int sm[256];
    int t = threadIdx.x;
    int v = (t < NB) ? g_blocksums[t] : 0;
    sm[t] = v;
    __syncthreads();
    for (int off = 1; off < 256; off <<= 1) {
        int u = (t >= off) ? sm[t - off] : 0;
        __syncthreads();
        sm[t] += u;
        __syncthreads();
    }
    if (t < NB) g_blocksums[t] = sm[t] - v;
}

__global__ void k_scan3(int N) {
    int i = blockIdx.x * 1024 + threadIdx.x;
    if (i < N) {
        int r = g_rowptr[i] + g_blocksums[blockIdx.x];
        g_rowptr[i] = r;
        g_pos[i] = r;
    }
}

// ---------------- CSR fill (4 edges/thread, batched) ------------------------
__global__ void k_fill(const void* __restrict__ ei, int E) {
    bool w64 = g_is64 != 0;
    int i = (blockIdx.x * blockDim.x + threadIdx.x) * 4;
    if (i >= E) return;
    int n = min(4, E - i);
    int s[4], d[4], pos[4];
    #pragma unroll
    for (int q = 0; q < 4; q++) if (q < n) {
        s[q] = ld_idx(ei, i + q, w64);
        d[q] = ld_idx(ei, (long long)E + i + q, w64);
    }
    #pragma unroll
    for (int q = 0; q < 4; q++) if (q < n) pos[q] = atomicAdd(&g_pos[d[q]], 1);
    #pragma unroll
    for (int q = 0; q < 4; q++) if (q < n) g_csr[pos[q]] = s[q];
}

// ---------------- propagation + LayerNorm + ReLU + pooling ------------------
// 2 nodes per warp: each 16-lane half owns one node's 256B row (uint4/lane).
// Both halves execute the same instruction stream on different edges:
// per edge cost = 0.5 LDG.128 + 1 SHFL + cvt/fma (vs 1 LDG + 2 SHFL before).
__global__ __launch_bounds__(256) void k_main(const void* __restrict__ batch,
                                              const float* __restrict__ b_conv,
                                              const float* __restrict__ gamma,
                                              const float* __restrict__ beta,
                                              int N) {
    const bool w64 = g_is64 != 0;
    int warp = threadIdx.x >> 5, lane = threadIdx.x & 31;
    int half = lane >> 4, hl = lane & 15;
    int slot = warp * 2 + half;              // 0..15
    int v = blockIdx.x * 16 + slot;
    __shared__ int   sgph[16];
    __shared__ float sstage[16][HDIM];       // 8 KB pooling stage
    __shared__ int   s_same;

    bool valid = v < N;
    float y[8];
    #pragma unroll
    for (int k = 0; k < 8; k++) y[k] = 0.f;
    int g = -1;
    const char* h1base = (const char*)g_h1b;

    float dv   = valid ? g_dinv[v] : 0.f;
    int   start = valid ? g_rowptr[v] : 0;
    int   cnt   = valid ? g_cnt[v] : 0;
    // warp-uniform upper bound over both halves
    int cnt_other = __shfl_xor_sync(0xffffffffu, cnt, 16);
    int umax = max(cnt, cnt_other);

    float acc[8];
    {
        // self contribution (row v), weight dv^2; zeros if invalid
        uint4 raw = valid ? *(const uint4*)(h1base + ((size_t)v << 8) + hl * 16)
                          : make_uint4(0u, 0u, 0u, 0u);
        float sw = dv * dv;
        const __nv_bfloat162* p = (const __nv_bfloat162*)&raw;
        #pragma unroll
        for (int k = 0; k < 4; k++) {
            float2 f = __bfloat1622float2(p[k]);
            acc[k * 2]     = sw * f.x;
            acc[k * 2 + 1] = sw * f.y;
        }
    }

    for (int base = 0; base < umax; base += 16) {
        int e = base + hl;
        int off = 0; float ww = 0.f;
        if (e < cnt) {
            int s = g_csr[start + e];
            off = s << 8;
            ww = g_dinv[s] * dv;
        }
        int m = min(16, umax - base);
        int j = 0;
        for (; j + 4 <= m; j += 4) {
            uint4 raw[4]; float wj[4];
            #pragma unroll
            for (int q = 0; q < 4; q++) {
                int srcl = (half << 4) + j + q;
                int oq = __shfl_sync(0xffffffffu, off, srcl);
                wj[q]  = __shfl_sync(0xffffffffu, ww, srcl);
                raw[q] = *(const uint4*)(h1base + oq + hl * 16);
            }
            #pragma unroll
            for (int q = 0; q < 4; q++) {
                const __nv_bfloat162* p = (const __nv_bfloat162*)&raw[q];
                #pragma unroll
                for (int k = 0; k < 4; k++) {
                    float2 f = __bfloat1622float2(p[k]);
                    acc[k * 2]     += wj[q] * f.x;
                    acc[k * 2 + 1] += wj[q] * f.y;
                }
            }
        }
        for (; j < m; j++) {
            int srcl = (half << 4) + j;
            int oq = __shfl_sync(0xffffffffu, off, srcl);
            float wj = __shfl_sync(0xffffffffu, ww, srcl);
            uint4 raw = *(const uint4*)(h1base + oq + hl * 16);
            const __nv_bfloat162* p = (const __nv_bfloat162*)&raw;
            #pragma unroll
            for (int k = 0; k < 4; k++) {
                float2 f = __bfloat1622float2(p[k]);
                acc[k * 2]     += wj * f.x;
                acc[k * 2 + 1] += wj * f.y;
            }
        }
    }

    if (valid) {
        // + b_conv (features hl*8 .. hl*8+7)
        float4 bc0 = *(const float4*)&b_conv[hl * 8];
        float4 bc1 = *(const float4*)&b_conv[hl * 8 + 4];
        acc[0] += bc0.x; acc[1] += bc0.y; acc[2] += bc0.z; acc[3] += bc0.w;
        acc[4] += bc1.x; acc[5] += bc1.y; acc[6] += bc1.z; acc[7] += bc1.w;
        // LayerNorm over 128 features: 8 local + 16-lane tree (stays in half)
        float sum = 0.f;
        #pragma unroll
        for (int k = 0; k < 8; k++) sum += acc[k];
        #pragma unroll
        for (int o = 8; o; o >>= 1) sum += __shfl_xor_sync(0xffffffffu, sum, o);
        float mu = sum * (1.f / 128.f);
        float sq = 0.f;
        #pragma unroll
        for (int k = 0; k < 8; k++) { acc[k] -= mu; sq += acc[k] * acc[k]; }
        #pragma unroll
        for (int o = 8; o; o >>= 1) sq += __shfl_xor_sync(0xffffffffu, sq, o);
        float inv = rsqrtf(sq * (1.f / 128.f) + 1e-5f);
        float4 ga0 = *(const float4*)&gamma[hl * 8];
        float4 ga1 = *(const float4*)&gamma[hl * 8 + 4];
        float4 be0 = *(const float4*)&beta[hl * 8];
        float4 be1 = *(const float4*)&beta[hl * 8 + 4];
        y[0] = fmaxf(0.f, ga0.x * acc[0] * inv + be0.x);
        y[1] = fmaxf(0.f, ga0.y * acc[1] * inv + be0.y);
        y[2] = fmaxf(0.f, ga0.z * acc[2] * inv + be0.z);
        y[3] = fmaxf(0.f, ga0.w * acc[3] * inv + be0.w);
        y[4] = fmaxf(0.f, ga1.x * acc[4] * inv + be1.x);
        y[5] = fmaxf(0.f, ga1.y * acc[5] * inv + be1.y);
        y[6] = fmaxf(0.f, ga1.z * acc[6] * inv + be1.z);
        y[7] = fmaxf(0.f, ga1.w * acc[7] * inv + be1.w);
        g = ld_idx(batch, v, w64);
    }

    // pooling: stage rows (zeros if invalid), tree-reduce, 1 atomic/feature
    if (hl == 0) sgph[slot] = valid ? g : -1;
    *(float4*)&sstage[slot][hl * 8]     = make_float4(y[0], y[1], y[2], y[3]);
    *(float4*)&sstage[slot][hl * 8 + 4] = make_float4(y[4], y[5], y[6], y[7]);
    __syncthreads();
    if (threadIdx.x == 0) {
        int g0 = -1; bool same = true;
        for (int i = 0; i < 16; i++) {
            int gi = sgph[i];
            if (gi >= 0) { if (g0 < 0) g0 = gi; else if (gi != g0) same = false; }
        }
        s_same = same ? g0 : -2;
    }
    __syncthreads();
    int smflag = s_same;
    if (smflag == -2) {
        // mixed-graph block (rare): per-lane atomics from registers
        if (valid) {
            float* ro = &g_readout[(size_t)g * HDIM + hl * 8];
            #pragma unroll
            for (int k = 0; k < 8; k++) atomicAdd(ro + k, y[k]);
        }
    } else if (smflag >= 0 && threadIdx.x < HDIM) {
        float a = 0.f;
        #pragma unroll
        for (int w = 0; w < 16; w++) a += sstage[w][threadIdx.x];
        atomicAdd(&g_readout[(size_t)smflag * HDIM + threadIdx.x], a);
    }
}

// ---------------- epilogue GEMM: out = readout @ W_post + b_post ------------
__global__ void k_out(const float* __restrict__ Wp, const float* __restrict__ bp,
                      float* __restrict__ out) {
    __shared__ float r[HDIM];
    int b = blockIdx.x, j = threadIdx.x;   // 64 threads
    r[j]      = g_readout[(size_t)b * HDIM + j];
    r[j + 64] = g_readout[(size_t)b * HDIM + j + 64];
    __syncthreads();
    float acc = bp[j];
    #pragma unroll 8
    for (int k = 0; k < HDIM; k++) acc += r[k] * Wp[k * CDIM + j];
    out[b * CDIM + j] = acc;
}

// ---------------- launch ----------------------------------------------------
extern "C" void kernel_launch(void* const* d_in, const int* in_sizes, int n_in,
                              void* d_out, int out_size) {
    const float* x      = (const float*)d_in[0];
    const void*  ei     = d_in[1];
    const void*  batch  = d_in[2];
    const float* W_pre  = (const float*)d_in[3];
    const float* b_pre  = (const float*)d_in[4];
    const float* W_conv = (const float*)d_in[5];
    const float* b_conv = (const float*)d_in[6];
    const float* gamma  = (const float*)d_in[7];
    const float* beta   = (const float*)d_in[8];
    const float* W_post = (const float*)d_in[9];
    const float* b_post = (const float*)d_in[10];

    int N = in_sizes[0] / FDIM;
    int E = in_sizes[1] / 2;
    int G = out_size / CDIM;
    if (N > NMAX) N = NMAX;
    if (E > EMAX) E = EMAX;
    if (G > GMAX) G = GMAX;
    int NB = (N + 1023) / 1024;
    int numTiles = (N + 63) / 64;

    cudaFuncSetAttribute(k_gemm_mma, cudaFuncAttributeMaxDynamicSharedMemorySize, GEMM_SMEM);

    {
        int ZB = (N + G * HDIM + 255) / 256;
        k_init<<<ZB + 65, 256>>>((const int*)ei, W_pre, b_pre, W_conv, N, G, ZB);
    }

    if (s_fork_ok) {
        // fork: GEMM on side stream, CSR build on main stream, rejoin before k_main
        cudaEventRecord(s_ev1, 0);
        cudaStreamWaitEvent(s_side, s_ev1, 0);
        k_gemm_mma<<<GEMM_GRID, 256, GEMM_SMEM, s_side>>>(x, N, numTiles);
        cudaEventRecord(s_ev2, s_side);

        k_count<<<(E / 4 + 255) / 256, 256>>>(ei, E);
        k_scan1<<<NB, 1024>>>(N);
        k_scan2<<<1, 256>>>(NB);
        k_scan3<<<NB, 1024>>>(N);
        k_fill<<<(E / 4 + 255) / 256, 256>>>(ei, E);

        cudaStreamWaitEvent(0, s_ev2, 0);
    } else {
        k_gemm_mma<<<GEMM_GRID, 256, GEMM_SMEM>>>(x, N, numTiles);
        k_count<<<(E / 4 + 255) / 256, 256>>>(ei, E);
        k_scan1<<<NB, 1024>>>(N);
        k_scan2<<<1, 256>>>(NB);
        k_scan3<<<NB, 1024>>>(N);
        k_fill<<<(E / 4 + 255) / 256, 256>>>(ei, E);
    }

    k_main<<<(N + 15) / 16, 256>>>(batch, b_conv, gamma, beta, N);
    k_out<<<G, CDIM>>>(W_post, b_post, (float*)d_out);
}